// round 3
// baseline (speedup 1.0000x reference)
#include <cuda_runtime.h>

// d_ov[b*256 + c], 16B-aligned for float4 reads in the broadcast kernel.
__device__ __align__(16) float d_ov[8 * 256];

#define EPSF 1e-5f

// One block per batch row b (8 blocks, 256 threads). Thread index = channel c.
// ctx = param_tokens[b] @ Wparam + bparam        (16 MACs/thread)
// ln  = layernorm(ctx) * g + beta                (block reduction)
// v   = ln @ Wkv[:, 256:512]                     (256 MACs/thread, coalesced cols)
// ov  = v @ Wout + bout                          (256 MACs/thread, coalesced cols)
__global__ void __launch_bounds__(256, 1)
compute_ov_kernel(const float* __restrict__ param_tokens,  // (8,16)
                  const float* __restrict__ Wparam,        // (16,256)
                  const float* __restrict__ bparam,        // (256)
                  const float* __restrict__ ctx_g,         // (256)
                  const float* __restrict__ ctx_b,         // (256)
                  const float* __restrict__ Wkv,           // (256,512)
                  const float* __restrict__ Wout,          // (256,256)
                  const float* __restrict__ bout)          // (256)
{
    const int b = blockIdx.x;
    const int c = threadIdx.x;

    __shared__ float s_ln[256];
    __shared__ float s_v[256];
    __shared__ float s_red[16];

    // ---- ctx[c] ----
    float ctx = bparam[c];
    const float* pt = param_tokens + b * 16;
#pragma unroll
    for (int p = 0; p < 16; ++p)
        ctx = fmaf(__ldg(&pt[p]), Wparam[p * 256 + c], ctx);

    // ---- block reduce sum / sumsq over 256 channels ----
    float s = ctx, sq = ctx * ctx;
#pragma unroll
    for (int o = 16; o > 0; o >>= 1) {
        s  += __shfl_down_sync(0xffffffffu, s,  o);
        sq += __shfl_down_sync(0xffffffffu, sq, o);
    }
    const int warp = c >> 5, lane = c & 31;
    if (lane == 0) { s_red[warp] = s; s_red[8 + warp] = sq; }
    __syncthreads();
    if (warp == 0) {
        float ss = (lane < 8) ? s_red[lane]     : 0.0f;
        float qq = (lane < 8) ? s_red[8 + lane] : 0.0f;
#pragma unroll
        for (int o = 4; o > 0; o >>= 1) {
            ss += __shfl_down_sync(0xffffffffu, ss, o);
            qq += __shfl_down_sync(0xffffffffu, qq, o);
        }
        if (lane == 0) { s_red[0] = ss; s_red[1] = qq; }
    }
    __syncthreads();
    const float mean = s_red[0] * (1.0f / 256.0f);
    const float var  = s_red[1] * (1.0f / 256.0f) - mean * mean;
    const float rinv = rsqrtf(var + EPSF);

    s_ln[c] = fmaf((ctx - mean) * rinv, ctx_g[c], ctx_b[c]);
    __syncthreads();

    // ---- v[c] = ln . Wkv[:, 256 + c] ----  (only the V half; K is dead)
    {
        float a0 = 0.f, a1 = 0.f, a2 = 0.f, a3 = 0.f;
        const float* wk = Wkv + 256 + c;  // column c of V half, stride 512
#pragma unroll 4
        for (int i = 0; i < 256; i += 4) {
            a0 = fmaf(s_ln[i + 0], wk[(i + 0) * 512], a0);
            a1 = fmaf(s_ln[i + 1], wk[(i + 1) * 512], a1);
            a2 = fmaf(s_ln[i + 2], wk[(i + 2) * 512], a2);
            a3 = fmaf(s_ln[i + 3], wk[(i + 3) * 512], a3);
        }
        s_v[c] = (a0 + a1) + (a2 + a3);
    }
    __syncthreads();

    // ---- ov[c] = v . Wout[:, c] + bout[c] ----
    {
        float a0 = bout[c], a1 = 0.f, a2 = 0.f, a3 = 0.f;
        const float* wo = Wout + c;  // column c, stride 256
#pragma unroll 4
        for (int i = 0; i < 256; i += 4) {
            a0 = fmaf(s_v[i + 0], wo[(i + 0) * 256], a0);
            a1 = fmaf(s_v[i + 1], wo[(i + 1) * 256], a1);
            a2 = fmaf(s_v[i + 2], wo[(i + 2) * 256], a2);
            a3 = fmaf(s_v[i + 3], wo[(i + 3) * 256], a3);
        }
        d_ov[b * 256 + c] = (a0 + a1) + (a2 + a3);
    }
}

// out[b,n,c] = img[b,n,c] + ov[b,c].  float4-vectorized exact cover:
// total elems = 8*1024*256 = 2^21 floats = 2^19 float4 = 2048 blocks * 256 thr.
__global__ void __launch_bounds__(256, 8)
broadcast_add_kernel(const float4* __restrict__ img, float4* __restrict__ out)
{
    const int i = blockIdx.x * 256 + threadIdx.x;   // float4 index, 0..524287
    const int e = i << 2;                           // element index
    const int b = e >> 18;                          // N*C = 2^18 elems per batch
    const int c4 = (e & 255) >> 2;                  // float4 index within channel dim

    const float4 a = img[i];
    const float4 o = reinterpret_cast<const float4*>(d_ov)[b * 64 + c4];
    out[i] = make_float4(a.x + o.x, a.y + o.y, a.z + o.z, a.w + o.w);
}

extern "C" void kernel_launch(void* const* d_in, const int* in_sizes, int n_in,
                              void* d_out, int out_size)
{
    // metadata order:
    // 0 img_tokens (8,1024,256)  1 param_tokens (8,16)
    // 2 img_norm_g 3 img_norm_b  4 Wq            <- all dead
    // 5 Wparam (16,256)  6 bparam (256)
    // 7 ctx_norm_g (256) 8 ctx_norm_b (256)
    // 9 Wkv (256,512)   10 Wout (256,256)  11 bout (256)
    const float* img          = (const float*)d_in[0];
    const float* param_tokens = (const float*)d_in[1];
    const float* Wparam       = (const float*)d_in[5];
    const float* bparam       = (const float*)d_in[6];
    const float* ctx_g        = (const float*)d_in[7];
    const float* ctx_b        = (const float*)d_in[8];
    const float* Wkv          = (const float*)d_in[9];
    const float* Wout         = (const float*)d_in[10];
    const float* bout         = (const float*)d_in[11];
    float* out = (float*)d_out;

    compute_ov_kernel<<<8, 256>>>(param_tokens, Wparam, bparam,
                                  ctx_g, ctx_b, Wkv, Wout, bout);
    broadcast_add_kernel<<<2048, 256>>>((const float4*)img, (float4*)out);
}

// round 8
// speedup vs baseline: 1.3120x; 1.3120x over previous
#include <cuda_runtime.h>

// d_ov[b*256 + c], 16B-aligned for float4 reads in the broadcast kernel.
__device__ __align__(16) float d_ov[8 * 256];

#define EPSF 1e-5f

// One block per batch row b (8 blocks, 1024 threads).
// Thread t handles output channel c = t & 255, k-slice s = t >> 8 (4-way split
// of the 256-deep dot products -> 64 MACs per thread, fully unrolled).
__global__ void __launch_bounds__(1024, 1)
compute_ov_kernel(const float* __restrict__ param_tokens,  // (8,16)
                  const float* __restrict__ Wparam,        // (16,256)
                  const float* __restrict__ bparam,        // (256)
                  const float* __restrict__ ctx_g,         // (256)
                  const float* __restrict__ ctx_b,         // (256)
                  const float* __restrict__ Wkv,           // (256,512)
                  const float* __restrict__ Wout,          // (256,256)
                  const float* __restrict__ bout)          // (256)
{
    const int b   = blockIdx.x;
    const int tid = threadIdx.x;
    const int c   = tid & 255;
    const int s   = tid >> 8;          // 0..3
    const int kb  = s * 64;            // this thread's k-base

    __shared__ float s_ln[256];
    __shared__ float s_v[256];
    __shared__ float s_part[4 * 256];
    __shared__ float s_red[16];

    // Weight column pointers (coalesced across c). Independent of LN result,
    // so prefetch the first 16 GEMV-1 weights NOW — they land while the
    // ctx/layernorm phase runs, hiding the first DRAM latency.
    const float* wk = Wkv  + 256 + c + kb * 512;   // V-half column c, stride 512
    const float* wo = Wout + c       + kb * 256;   // Wout column c, stride 256

    float wpre[16];
#pragma unroll
    for (int i = 0; i < 16; ++i) wpre[i] = wk[i * 512];

    // ---- ctx[c] (s==0 threads only) + LN stats ----
    float ctx = 0.0f;
    if (s == 0) {
        ctx = bparam[c];
        const float* pt = param_tokens + b * 16;
#pragma unroll
        for (int p = 0; p < 16; ++p)
            ctx = fmaf(__ldg(&pt[p]), Wparam[p * 256 + c], ctx);

        float ss = ctx, qq = ctx * ctx;
#pragma unroll
        for (int o = 16; o > 0; o >>= 1) {
            ss += __shfl_down_sync(0xffffffffu, ss, o);
            qq += __shfl_down_sync(0xffffffffu, qq, o);
        }
        const int warp = tid >> 5, lane = tid & 31;   // warps 0..7
        if (lane == 0) { s_red[warp] = ss; s_red[8 + warp] = qq; }
    }
    __syncthreads();
    if (tid < 32) {
        float ss = (tid < 8) ? s_red[tid]     : 0.0f;
        float qq = (tid < 8) ? s_red[8 + tid] : 0.0f;
#pragma unroll
        for (int o = 4; o > 0; o >>= 1) {
            ss += __shfl_down_sync(0xffffffffu, ss, o);
            qq += __shfl_down_sync(0xffffffffu, qq, o);
        }
        if (tid == 0) { s_red[0] = ss; s_red[1] = qq; }
    }
    __syncthreads();
    if (s == 0) {
        const float mean = s_red[0] * (1.0f / 256.0f);
        const float var  = s_red[1] * (1.0f / 256.0f) - mean * mean;
        const float rinv = rsqrtf(var + EPSF);
        s_ln[c] = fmaf((ctx - mean) * rinv, ctx_g[c], ctx_b[c]);
    }
    __syncthreads();

    // ---- GEMV1 partial: v_part = sum_{i in slice} ln[kb+i] * Wkv_V[kb+i][c] ----
    {
        float a0 = 0.f, a1 = 0.f, a2 = 0.f, a3 = 0.f;
#pragma unroll
        for (int i = 0; i < 16; ++i) {
            float acc = fmaf(s_ln[kb + i], wpre[i], 0.0f);
            if ((i & 3) == 0) a0 += acc; else if ((i & 3) == 1) a1 += acc;
            else if ((i & 3) == 2) a2 += acc; else a3 += acc;
        }
#pragma unroll
        for (int i = 16; i < 64; i += 4) {
            a0 = fmaf(s_ln[kb + i + 0], wk[(i + 0) * 512], a0);
            a1 = fmaf(s_ln[kb + i + 1], wk[(i + 1) * 512], a1);
            a2 = fmaf(s_ln[kb + i + 2], wk[(i + 2) * 512], a2);
            a3 = fmaf(s_ln[kb + i + 3], wk[(i + 3) * 512], a3);
        }
        s_part[tid] = (a0 + a1) + (a2 + a3);
    }
    __syncthreads();
    if (s == 0)
        s_v[c] = s_part[c] + s_part[256 + c] + s_part[512 + c] + s_part[768 + c];
    __syncthreads();

    // ---- GEMV2 partial: ov_part = sum_{i in slice} v[kb+i] * Wout[kb+i][c] ----
    {
        float a0 = 0.f, a1 = 0.f, a2 = 0.f, a3 = 0.f;
#pragma unroll
        for (int i = 0; i < 64; i += 4) {
            a0 = fmaf(s_v[kb + i + 0], wo[(i + 0) * 256], a0);
            a1 = fmaf(s_v[kb + i + 1], wo[(i + 1) * 256], a1);
            a2 = fmaf(s_v[kb + i + 2], wo[(i + 2) * 256], a2);
            a3 = fmaf(s_v[kb + i + 3], wo[(i + 3) * 256], a3);
        }
        s_part[tid] = (a0 + a1) + (a2 + a3);
    }
    __syncthreads();
    if (s == 0)
        d_ov[b * 256 + c] = bout[c] + s_part[c] + s_part[256 + c]
                          + s_part[512 + c] + s_part[768 + c];
}

// out[b,n,c] = img[b,n,c] + ov[b,c].
// 512 blocks x 256 threads; each thread handles 4 float4s strided by 131072
// (= total threads). Stride is a multiple of 64 float4s, so c4 is constant per
// thread; batch index advances by 2 per stride step. MLP_p1 = 4 (front-batched).
__global__ void __launch_bounds__(256, 8)
broadcast_add_kernel(const float4* __restrict__ img, float4* __restrict__ out)
{
    const int t  = blockIdx.x * 256 + threadIdx.x;   // 0..131071
    const int c4 = t & 63;
    const int b0 = t >> 16;                          // 0 or 1
    const float4* ovp = reinterpret_cast<const float4*>(d_ov);

    // front-batched loads
    const float4 a0 = img[t];
    const float4 a1 = img[t + 131072];
    const float4 a2 = img[t + 262144];
    const float4 a3 = img[t + 393216];
    const float4 o0 = ovp[(b0 + 0) * 64 + c4];
    const float4 o1 = ovp[(b0 + 2) * 64 + c4];
    const float4 o2 = ovp[(b0 + 4) * 64 + c4];
    const float4 o3 = ovp[(b0 + 6) * 64 + c4];

    out[t]          = make_float4(a0.x + o0.x, a0.y + o0.y, a0.z + o0.z, a0.w + o0.w);
    out[t + 131072] = make_float4(a1.x + o1.x, a1.y + o1.y, a1.z + o1.z, a1.w + o1.w);
    out[t + 262144] = make_float4(a2.x + o2.x, a2.y + o2.y, a2.z + o2.z, a2.w + o2.w);
    out[t + 393216] = make_float4(a3.x + o3.x, a3.y + o3.y, a3.z + o3.z, a3.w + o3.w);
}

extern "C" void kernel_launch(void* const* d_in, const int* in_sizes, int n_in,
                              void* d_out, int out_size)
{
    // metadata order:
    // 0 img_tokens (8,1024,256)  1 param_tokens (8,16)
    // 2 img_norm_g 3 img_norm_b  4 Wq            <- all dead (softmax collapse)
    // 5 Wparam (16,256)  6 bparam (256)
    // 7 ctx_norm_g (256) 8 ctx_norm_b (256)
    // 9 Wkv (256,512)   10 Wout (256,256)  11 bout (256)
    const float* img          = (const float*)d_in[0];
    const float* param_tokens = (const float*)d_in[1];
    const float* Wparam       = (const float*)d_in[5];
    const float* bparam       = (const float*)d_in[6];
    const float* ctx_g        = (const float*)d_in[7];
    const float* ctx_b        = (const float*)d_in[8];
    const float* Wkv          = (const float*)d_in[9];
    const float* Wout         = (const float*)d_in[10];
    const float* bout         = (const float*)d_in[11];
    float* out = (float*)d_out;

    compute_ov_kernel<<<8, 1024>>>(param_tokens, Wparam, bparam,
                                   ctx_g, ctx_b, Wkv, Wout, bout);
    broadcast_add_kernel<<<512, 256>>>((const float4*)img, (float4*)out);
}